// round 2
// baseline (speedup 1.0000x reference)
#include <cuda_runtime.h>
#include <cuda_bf16.h>
#include <math.h>

// ---------------- problem constants ----------------
#define BB    4096
#define TT    96
#define FRAW  5
#define TOTF  11
#define HID   512
#define NL    4
#define HEADS 8
#define DH    64
#define PATCH 8
#define NPATCH 12
#define PDIM  88            // PATCH * TOTF
#define TOK   (BB*NPATCH)   // 49152
#define MLPH  2048
#define NCLS  3

// ---------------- scratch (static device, no allocation) ----------------
__device__ float g_feats[(size_t)TOK*PDIM];
__device__ float g_h  [(size_t)TOK*HID];
__device__ float g_h2 [(size_t)TOK*HID];
__device__ float g_n  [(size_t)TOK*HID];
__device__ float g_qkv[(size_t)TOK*3*HID];
__device__ float g_o  [(size_t)TOK*HID];
__device__ float g_g  [(size_t)TOK*MLPH];
__device__ float g_c1 [(size_t)BB*512];
__device__ float g_c2 [(size_t)BB*128];

__device__ __forceinline__ float gelu_f(float x) {
    return 0.5f * x * (1.f + erff(x * 0.7071067811865476f));
}

// ---------------- stage 1: factor engineering + time-norm ----------------
// one block per batch row, 96 threads (one per timestep)
__global__ void factors_kernel(const float* __restrict__ x,
                               const float* __restrict__ in_w,
                               const float* __restrict__ in_b,
                               float* __restrict__ feats)
{
    __shared__ float cl[TT], vol[TT];
    __shared__ float sf[TT][TOTF];
    __shared__ float mean_s[TOTF], inv_s[TOTF];
    const int b = blockIdx.x;
    const int t = threadIdx.x;
    const float* xb = x + (size_t)b * TT * FRAW;

    if (t < TT) {
        cl[t]  = xb[t*FRAW + 3];
        vol[t] = xb[t*FRAW + 4];
    }
    __syncthreads();

    if (t < TT) {
        const float a13 = 2.f/13.f, a27 = 2.f/27.f, a14 = 1.f/14.f;
        float e13 = cl[0], e27 = cl[0];
        float eg = 0.f, el = 0.f;       // gain[0]=loss[0]=0 -> ema init 0
        for (int j = 1; j <= t; j++) {
            float c = cl[j];
            e13 = a13*c + (1.f - a13)*e13;
            e27 = a27*c + (1.f - a27)*e27;
            float d = c - cl[j-1];
            float g = fmaxf(d, 0.f);
            float l = -fminf(d, 0.f);
            eg = a14*g + (1.f - a14)*eg;
            el = a14*l + (1.f - a14)*el;
        }
        float macd = e13 - e27;
        float rs  = eg / (el + 1e-10f);
        float rsi = (100.f - 100.f/(1.f + rs)) * 0.01f;

        float bb = 0.f;
        if (t >= 19) {
            float s = 0.f, s2 = 0.f;
            for (int j = t-19; j <= t; j++) { float c = cl[j]; s += c; s2 += c*c; }
            float m  = s * 0.05f;
            float sq = s2 * 0.05f;
            float sd = sqrtf(fmaxf(sq - m*m, 0.f));
            bb = 4.f * sd / (m + 1e-8f);
        }

        float lr = 0.f, lv = 0.f;
        float svt = vol[t] > 0.f ? vol[t] : 1.f;
        if (t >= 1) {
            float pc = fmaxf(cl[t-1], 1e-8f);
            lr = logf(fmaxf(cl[t], 1e-8f) / pc);
            float svp = vol[t-1] > 0.f ? vol[t-1] : 1.f;
            lv = logf(svt / (svp + 1e-8f));
        }

        float vmr = 1.f;
        if (t >= 19) {
            float s = 0.f;
            for (int j = t-19; j <= t; j++) { float v2 = vol[j] > 0.f ? vol[j] : 1.f; s += v2; }
            vmr = svt / (s * 0.05f + 1e-8f);
        }

        float f6[6] = {macd, rsi, bb, lr, lv, vmr};
        #pragma unroll
        for (int f = 0; f < FRAW; f++) sf[t][f] = xb[t*FRAW + f];
        #pragma unroll
        for (int f = 0; f < 6; f++) {
            float v = f6[f];
            if (!isfinite(v)) v = 0.f;
            sf[t][FRAW + f] = v;
        }
    }
    __syncthreads();

    if (t < TOTF) {
        float s = 0.f;
        for (int j = 0; j < TT; j++) s += sf[j][t];
        mean_s[t] = s / (float)TT;
    }
    __syncthreads();
    if (t < TOTF) {
        float m = mean_s[t], s = 0.f;
        for (int j = 0; j < TT; j++) { float d = sf[j][t] - m; s += d*d; }
        inv_s[t] = rsqrtf(s / (float)TT + 1e-5f);
    }
    __syncthreads();

    if (t < TT) {
        float* o = feats + ((size_t)b*TT + t) * TOTF;
        #pragma unroll
        for (int f = 0; f < TOTF; f++)
            o[f] = (sf[t][f] - mean_s[f]) * inv_s[f] * in_w[f] + in_b[f];
    }
}

// ---------------- LayerNorm over last dim 512 (one block per token) ------
__global__ void __launch_bounds__(128) ln_kernel(const float* __restrict__ X,
                                                 const float* __restrict__ w,
                                                 const float* __restrict__ b,
                                                 float* __restrict__ Y)
{
    const int row = blockIdx.x;
    const int tid = threadIdx.x;
    const float4 v = ((const float4*)(X + (size_t)row*HID))[tid];
    float s = v.x + v.y + v.z + v.w;
    __shared__ float red[4], red2[4];
    #pragma unroll
    for (int o = 16; o; o >>= 1) s += __shfl_down_sync(0xffffffffu, s, o);
    if ((tid & 31) == 0) red[tid >> 5] = s;
    __syncthreads();
    const float m = (red[0]+red[1]+red[2]+red[3]) * (1.f/(float)HID);
    float dx = v.x - m, dy = v.y - m, dz = v.z - m, dw = v.w - m;
    float s2 = dx*dx + dy*dy + dz*dz + dw*dw;
    #pragma unroll
    for (int o = 16; o; o >>= 1) s2 += __shfl_down_sync(0xffffffffu, s2, o);
    if ((tid & 31) == 0) red2[tid >> 5] = s2;
    __syncthreads();
    const float var = (red2[0]+red2[1]+red2[2]+red2[3]) * (1.f/(float)HID);
    const float inv = rsqrtf(var + 1e-5f);
    const int c = tid * 4;
    const float4 wv = *(const float4*)(w + c);
    const float4 bv = *(const float4*)(b + c);
    float4 o4;
    o4.x = dx*inv*wv.x + bv.x;
    o4.y = dy*inv*wv.y + bv.y;
    o4.z = dz*inv*wv.z + bv.z;
    o4.w = dw*inv*wv.w + bv.w;
    ((float4*)(Y + (size_t)row*HID))[tid] = o4;
}

// ---------------- tiled SGEMM: C = act(A@B + bias [+ res]) ---------------
// A: MxK row-major, B: KxN row-major. All dims divisible: M%128==0, N%128==0, K%8==0.
#define GBM 128
#define GBN 128
#define GBK 8
template<int ACT, bool RES>
__global__ void __launch_bounds__(256) gemm_kernel(
    const float* __restrict__ A, const float* __restrict__ Bw,
    const float* __restrict__ bias, const float* __restrict__ res,
    float* __restrict__ C, int M, int N, int K)
{
    __shared__ float As[GBK][GBM];
    __shared__ float Bs[GBK][GBN];
    const int bx = blockIdx.x;   // N tile
    const int by = blockIdx.y;   // M tile
    const int tid = threadIdx.x;
    const int tcol = tid & 15;
    const int trow = tid >> 4;

    const float* Ab = A + (size_t)by * GBM * K;
    const float* Bb = Bw + (size_t)bx * GBN;

    float acc[8][8] = {};

    const int aRow = tid >> 1;
    const int aCol = (tid & 1) * 4;
    const int bRow = tid >> 5;
    const int bCol = (tid & 31) * 4;

    for (int k0 = 0; k0 < K; k0 += GBK) {
        float4 av = *(const float4*)(Ab + (size_t)aRow*K + k0 + aCol);
        As[aCol+0][aRow] = av.x;
        As[aCol+1][aRow] = av.y;
        As[aCol+2][aRow] = av.z;
        As[aCol+3][aRow] = av.w;
        *(float4*)(&Bs[bRow][bCol]) = *(const float4*)(Bb + (size_t)(k0 + bRow)*N + bCol);
        __syncthreads();
        #pragma unroll
        for (int k = 0; k < GBK; k++) {
            float4 a0 = *(const float4*)(&As[k][trow*8]);
            float4 a1 = *(const float4*)(&As[k][trow*8+4]);
            float4 b0 = *(const float4*)(&Bs[k][tcol*8]);
            float4 b1 = *(const float4*)(&Bs[k][tcol*8+4]);
            float ar[8] = {a0.x,a0.y,a0.z,a0.w,a1.x,a1.y,a1.z,a1.w};
            float br[8] = {b0.x,b0.y,b0.z,b0.w,b1.x,b1.y,b1.z,b1.w};
            #pragma unroll
            for (int i = 0; i < 8; i++)
                #pragma unroll
                for (int j = 0; j < 8; j++)
                    acc[i][j] = fmaf(ar[i], br[j], acc[i][j]);
        }
        __syncthreads();
    }

    const int rowBase = by*GBM + trow*8;
    const int colBase = bx*GBN + tcol*8;
    #pragma unroll
    for (int i = 0; i < 8; i++) {
        const size_t roff = (size_t)(rowBase + i) * N + colBase;
        #pragma unroll
        for (int j = 0; j < 8; j++) {
            float v = acc[i][j] + bias[colBase + j];
            if (RES) v += res[roff + j];
            if (ACT == 1) v = gelu_f(v);
            C[roff + j] = v;
        }
    }
}

// ---------------- attention: block per (b, head), 64 threads -------------
__global__ void __launch_bounds__(64) attn_kernel(const float* __restrict__ qkv,
                                                  float* __restrict__ out)
{
    const int bh = blockIdx.x;
    const int b = bh >> 3, h = bh & 7;
    const int tid = threadIdx.x;
    __shared__ float q[NPATCH][DH], k[NPATCH][DH], v[NPATCH][DH];
    __shared__ float att[NPATCH][NPATCH];

    const float* base = qkv + (size_t)(b*NPATCH) * (3*HID) + h*DH;
    for (int idx = tid; idx < NPATCH*DH; idx += 64) {
        int p = idx >> 6, d = idx & 63;
        q[p][d] = base[(size_t)p*(3*HID) + d];
        k[p][d] = base[(size_t)p*(3*HID) + HID + d];
        v[p][d] = base[(size_t)p*(3*HID) + 2*HID + d];
    }
    __syncthreads();

    for (int p = tid; p < NPATCH*NPATCH; p += 64) {
        int i = p / NPATCH, j = p % NPATCH;
        float s = 0.f;
        #pragma unroll
        for (int d = 0; d < DH; d++) s = fmaf(q[i][d], k[j][d], s);
        att[i][j] = s * 0.125f;   // 1/sqrt(64)
    }
    __syncthreads();

    if (tid < NPATCH) {
        float mx = -1e30f;
        #pragma unroll
        for (int j = 0; j < NPATCH; j++) mx = fmaxf(mx, att[tid][j]);
        float e[NPATCH], sum = 0.f;
        #pragma unroll
        for (int j = 0; j < NPATCH; j++) { e[j] = expf(att[tid][j] - mx); sum += e[j]; }
        const float r = 1.f / sum;
        #pragma unroll
        for (int j = 0; j < NPATCH; j++) att[tid][j] = e[j] * r;
    }
    __syncthreads();

    const int d = tid;  // 64 threads, one head-dim column each
    #pragma unroll
    for (int i = 0; i < NPATCH; i++) {
        float s = 0.f;
        #pragma unroll
        for (int j = 0; j < NPATCH; j++) s = fmaf(att[i][j], v[j][d], s);
        out[(size_t)(b*NPATCH + i)*HID + h*DH + d] = s;
    }
}

// ---------------- final tiny GEMM: (4096x128)@(128x3) --------------------
__global__ void cls3_kernel(const float* __restrict__ C2,
                            const float* __restrict__ w3,
                            const float* __restrict__ b3,
                            float* __restrict__ out)
{
    const int idx = blockIdx.x * blockDim.x + threadIdx.x;
    if (idx >= BB*NCLS) return;
    const int b = idx / NCLS, c = idx % NCLS;
    float s = b3[c];
    const float* r = C2 + (size_t)b*128;
    #pragma unroll 8
    for (int k2 = 0; k2 < 128; k2++) s = fmaf(r[k2], w3[k2*NCLS + c], s);
    out[idx] = s;
}

// ---------------- host launcher ------------------------------------------
static inline float* sym_addr(const void* s) {
    void* p = nullptr;
    cudaGetSymbolAddress(&p, s);
    return (float*)p;
}

extern "C" void kernel_launch(void* const* d_in, const int* in_sizes, int n_in,
                              void* d_out, int out_size)
{
    const float* x      = (const float*)d_in[0];
    const float* in_w   = (const float*)d_in[1];
    const float* in_b   = (const float*)d_in[2];
    const float* pe_w   = (const float*)d_in[3];
    const float* pe_b   = (const float*)d_in[4];
    const float* ln1_w  = (const float*)d_in[5];
    const float* ln1_b  = (const float*)d_in[6];
    const float* qkv_w  = (const float*)d_in[7];
    const float* qkv_b  = (const float*)d_in[8];
    const float* out_w  = (const float*)d_in[9];
    const float* out_b  = (const float*)d_in[10];
    const float* ln2_w  = (const float*)d_in[11];
    const float* ln2_b  = (const float*)d_in[12];
    const float* mlp_w1 = (const float*)d_in[13];
    const float* mlp_b1 = (const float*)d_in[14];
    const float* mlp_w2 = (const float*)d_in[15];
    const float* mlp_b2 = (const float*)d_in[16];
    const float* cls_w1 = (const float*)d_in[17];
    const float* cls_b1 = (const float*)d_in[18];
    const float* cls_w2 = (const float*)d_in[19];
    const float* cls_b2 = (const float*)d_in[20];
    const float* cls_w3 = (const float*)d_in[21];
    const float* cls_b3 = (const float*)d_in[22];

    float* F   = sym_addr(g_feats);
    float* H   = sym_addr(g_h);
    float* H2  = sym_addr(g_h2);
    float* Nn  = sym_addr(g_n);
    float* QKV = sym_addr(g_qkv);
    float* O   = sym_addr(g_o);
    float* G   = sym_addr(g_g);
    float* C1  = sym_addr(g_c1);
    float* C2  = sym_addr(g_c2);

    // stage 1: features
    factors_kernel<<<BB, TT>>>(x, in_w, in_b, F);

    // patch embed: (TOK x 88) @ (88 x 512)
    gemm_kernel<0,false><<<dim3(HID/GBN, TOK/GBM), 256>>>(F, pe_w, pe_b, nullptr, H, TOK, HID, PDIM);

    for (int i = 0; i < NL; i++) {
        ln_kernel<<<TOK, 128>>>(H, ln1_w + i*HID, ln1_b + i*HID, Nn);
        gemm_kernel<0,false><<<dim3(3*HID/GBN, TOK/GBM), 256>>>(
            Nn, qkv_w + (size_t)i*HID*3*HID, qkv_b + (size_t)i*3*HID, nullptr, QKV, TOK, 3*HID, HID);
        attn_kernel<<<BB*HEADS, 64>>>(QKV, O);
        gemm_kernel<0,true><<<dim3(HID/GBN, TOK/GBM), 256>>>(
            O, out_w + (size_t)i*HID*HID, out_b + (size_t)i*HID, H, H2, TOK, HID, HID);
        ln_kernel<<<TOK, 128>>>(H2, ln2_w + i*HID, ln2_b + i*HID, Nn);
        gemm_kernel<1,false><<<dim3(MLPH/GBN, TOK/GBM), 256>>>(
            Nn, mlp_w1 + (size_t)i*HID*MLPH, mlp_b1 + (size_t)i*MLPH, nullptr, G, TOK, MLPH, HID);
        gemm_kernel<0,true><<<dim3(HID/GBN, TOK/GBM), 256>>>(
            G, mlp_w2 + (size_t)i*MLPH*HID, mlp_b2 + (size_t)i*HID, H2, H, TOK, HID, MLPH);
    }

    // classifier: H viewed as (4096 x 6144)
    gemm_kernel<1,false><<<dim3(512/GBN, BB/GBM), 256>>>(H, cls_w1, cls_b1, nullptr, C1, BB, 512, HID*NPATCH);
    gemm_kernel<1,false><<<dim3(128/GBN, BB/GBM), 256>>>(C1, cls_w2, cls_b2, nullptr, C2, BB, 128, 512);
    cls3_kernel<<<(BB*NCLS + 127)/128, 128>>>(C2, cls_w3, cls_b3, (float*)d_out);
}

// round 5
// speedup vs baseline: 2.5910x; 2.5910x over previous
#include <cuda_runtime.h>
#include <cuda_bf16.h>
#include <math.h>
#include <stdint.h>

// ---------------- problem constants ----------------
#define BB    4096
#define TT    96
#define FRAW  5
#define TOTF  11
#define HID   512
#define NL    4
#define HEADS 8
#define DH    64
#define PATCH 8
#define NPATCH 12
#define PDIM  88            // PATCH * TOTF
#define PDIMP 96            // padded to multiple of 16
#define TOK   (BB*NPATCH)   // 49152
#define MLPH  2048
#define NCLS  3

// ---------------- scratch (static device, no allocation) ----------------
__device__ float g_feats[(size_t)TOK*PDIMP];
__device__ float g_pew [(size_t)PDIMP*HID];
__device__ float g_h  [(size_t)TOK*HID];
__device__ float g_h2 [(size_t)TOK*HID];
__device__ float g_n  [(size_t)TOK*HID];
__device__ float g_qkv[(size_t)TOK*3*HID];
__device__ float g_o  [(size_t)TOK*HID];
__device__ float g_g  [(size_t)TOK*MLPH];
__device__ float g_c1 [(size_t)BB*512];
__device__ float g_c2 [(size_t)BB*128];

__device__ __forceinline__ float gelu_f(float x) {
    return 0.5f * x * (1.f + erff(x * 0.7071067811865476f));
}

__device__ __forceinline__ float to_tf32(float x) {
    uint32_t u;
    asm("cvt.rna.tf32.f32 %0, %1;" : "=r"(u) : "f"(x));
    return __uint_as_float(u);
}

__device__ __forceinline__ void mma_tf32(float c[4], const uint32_t a[4], const uint32_t b[2]) {
    asm volatile(
        "mma.sync.aligned.m16n8k8.row.col.f32.tf32.tf32.f32 "
        "{%0,%1,%2,%3}, {%4,%5,%6,%7}, {%8,%9}, {%0,%1,%2,%3};"
        : "+f"(c[0]), "+f"(c[1]), "+f"(c[2]), "+f"(c[3])
        : "r"(a[0]), "r"(a[1]), "r"(a[2]), "r"(a[3]), "r"(b[0]), "r"(b[1]));
}

// ---------------- stage 1: factor engineering + time-norm ----------------
// one block per batch row, 96 threads (one per timestep)
// OUTPUT: padded patch layout  feats[token][96], cols 88..95 = 0
__global__ void factors_kernel(const float* __restrict__ x,
                               const float* __restrict__ in_w,
                               const float* __restrict__ in_b,
                               float* __restrict__ feats)
{
    __shared__ float cl[TT], vol[TT];
    __shared__ float sf[TT][TOTF];
    __shared__ float mean_s[TOTF], inv_s[TOTF];
    const int b = blockIdx.x;
    const int t = threadIdx.x;
    const float* xb = x + (size_t)b * TT * FRAW;

    if (t < TT) {
        cl[t]  = xb[t*FRAW + 3];
        vol[t] = xb[t*FRAW + 4];
    }
    __syncthreads();

    if (t < TT) {
        const float a13 = 2.f/13.f, a27 = 2.f/27.f, a14 = 1.f/14.f;
        float e13 = cl[0], e27 = cl[0];
        float eg = 0.f, el = 0.f;
        for (int j = 1; j <= t; j++) {
            float c = cl[j];
            e13 = a13*c + (1.f - a13)*e13;
            e27 = a27*c + (1.f - a27)*e27;
            float d = c - cl[j-1];
            float g = fmaxf(d, 0.f);
            float l = -fminf(d, 0.f);
            eg = a14*g + (1.f - a14)*eg;
            el = a14*l + (1.f - a14)*el;
        }
        float macd = e13 - e27;
        float rs  = eg / (el + 1e-10f);
        float rsi = (100.f - 100.f/(1.f + rs)) * 0.01f;

        float bb = 0.f;
        if (t >= 19) {
            float s = 0.f, s2 = 0.f;
            for (int j = t-19; j <= t; j++) { float c = cl[j]; s += c; s2 += c*c; }
            float m  = s * 0.05f;
            float sq = s2 * 0.05f;
            float sd = sqrtf(fmaxf(sq - m*m, 0.f));
            bb = 4.f * sd / (m + 1e-8f);
        }

        float lr = 0.f, lv = 0.f;
        float svt = vol[t] > 0.f ? vol[t] : 1.f;
        if (t >= 1) {
            float pc = fmaxf(cl[t-1], 1e-8f);
            lr = logf(fmaxf(cl[t], 1e-8f) / pc);
            float svp = vol[t-1] > 0.f ? vol[t-1] : 1.f;
            lv = logf(svt / (svp + 1e-8f));
        }

        float vmr = 1.f;
        if (t >= 19) {
            float s = 0.f;
            for (int j = t-19; j <= t; j++) { float v2 = vol[j] > 0.f ? vol[j] : 1.f; s += v2; }
            vmr = svt / (s * 0.05f + 1e-8f);
        }

        float f6[6] = {macd, rsi, bb, lr, lv, vmr};
        #pragma unroll
        for (int f = 0; f < FRAW; f++) sf[t][f] = xb[t*FRAW + f];
        #pragma unroll
        for (int f = 0; f < 6; f++) {
            float v = f6[f];
            if (!isfinite(v)) v = 0.f;
            sf[t][FRAW + f] = v;
        }
    }
    __syncthreads();

    if (t < TOTF) {
        float s = 0.f;
        for (int j = 0; j < TT; j++) s += sf[j][t];
        mean_s[t] = s / (float)TT;
    }
    __syncthreads();
    if (t < TOTF) {
        float m = mean_s[t], s = 0.f;
        for (int j = 0; j < TT; j++) { float d = sf[j][t] - m; s += d*d; }
        inv_s[t] = rsqrtf(s / (float)TT + 1e-5f);
    }
    __syncthreads();

    if (t < TT) {
        const int token = b*NPATCH + (t / PATCH);
        float* o = feats + (size_t)token*PDIMP + (t % PATCH)*TOTF;
        #pragma unroll
        for (int f = 0; f < TOTF; f++)
            o[f] = (sf[t][f] - mean_s[f]) * inv_s[f] * in_w[f] + in_b[f];
    }
    // zero the 8-column pad of each token
    if (t < NPATCH) {
        float* z = feats + (size_t)(b*NPATCH + t)*PDIMP + PDIM;
        #pragma unroll
        for (int i = 0; i < PDIMP - PDIM; i++) z[i] = 0.f;
    }
}

// pad pe_w (88x512) -> g_pew (96x512, zero rows 88..95)
__global__ void pad_pew_kernel(const float* __restrict__ pe_w, float* __restrict__ dst)
{
    const int idx = blockIdx.x * blockDim.x + threadIdx.x;
    if (idx >= PDIMP*HID) return;
    const int k = idx / HID, n = idx % HID;
    dst[idx] = (k < PDIM) ? pe_w[k*HID + n] : 0.f;
}

// ---------------- LayerNorm over last dim 512 (one block per token) ------
__global__ void __launch_bounds__(128) ln_kernel(const float* __restrict__ X,
                                                 const float* __restrict__ w,
                                                 const float* __restrict__ b,
                                                 float* __restrict__ Y)
{
    const int row = blockIdx.x;
    const int tid = threadIdx.x;
    const float4 v = ((const float4*)(X + (size_t)row*HID))[tid];
    float s = v.x + v.y + v.z + v.w;
    __shared__ float red[4], red2[4];
    #pragma unroll
    for (int o = 16; o; o >>= 1) s += __shfl_down_sync(0xffffffffu, s, o);
    if ((tid & 31) == 0) red[tid >> 5] = s;
    __syncthreads();
    const float m = (red[0]+red[1]+red[2]+red[3]) * (1.f/(float)HID);
    float dx = v.x - m, dy = v.y - m, dz = v.z - m, dw = v.w - m;
    float s2 = dx*dx + dy*dy + dz*dz + dw*dw;
    #pragma unroll
    for (int o = 16; o; o >>= 1) s2 += __shfl_down_sync(0xffffffffu, s2, o);
    if ((tid & 31) == 0) red2[tid >> 5] = s2;
    __syncthreads();
    const float var = (red2[0]+red2[1]+red2[2]+red2[3]) * (1.f/(float)HID);
    const float inv = rsqrtf(var + 1e-5f);
    const int c = tid * 4;
    const float4 wv = *(const float4*)(w + c);
    const float4 bv = *(const float4*)(b + c);
    float4 o4;
    o4.x = dx*inv*wv.x + bv.x;
    o4.y = dy*inv*wv.y + bv.y;
    o4.z = dz*inv*wv.z + bv.z;
    o4.w = dw*inv*wv.w + bv.w;
    ((float4*)(Y + (size_t)row*HID))[tid] = o4;
}

// ---------------- tf32 tensor-core GEMM ----------------------------------
// C = act(A@B + bias [+ res]).  A: MxK row-major, B: KxN row-major.
// M%128==0, N%128==0, K%16==0.
// Block tile 128x128x16, 8 warps, warp tile 32x64 via m16n8k8 tf32 mma.
#define SA 20    // As row stride (16 + 4 pad) -> conflict-free frag loads
#define SB 136   // Bs row stride (128 + 8 pad)

template<int ACT, bool RES>
__global__ void __launch_bounds__(256, 2) mma_gemm(
    const float* __restrict__ A, const float* __restrict__ Bw,
    const float* __restrict__ bias, const float* __restrict__ res,
    float* __restrict__ C, int M, int N, int K)
{
    __shared__ float As[128][SA];   // [m][k]
    __shared__ float Bs[16][SB];    // [k][n]

    const int tid  = threadIdx.x;
    const int lane = tid & 31;
    const int wid  = tid >> 5;
    const int g    = lane >> 2;     // groupID 0..7
    const int t4   = lane & 3;      // threadID_in_group 0..3
    const int wm   = wid & 3;       // 4 warps along M
    const int wn   = wid >> 2;      // 2 warps along N
    const int mBase = wm * 32;
    const int nBase = wn * 64;

    const float* Ab = A  + (size_t)blockIdx.y * 128 * K;
    const float* Bb = Bw + (size_t)blockIdx.x * 128;

    float acc[2][8][4] = {};

    for (int k0 = 0; k0 < K; k0 += 16) {
        // ---- stage A tile (128x16), vectorized, tf32-rounded ----
        #pragma unroll
        for (int i = 0; i < 2; i++) {
            const int f = tid + i*256;
            const int r = f >> 2, kq = (f & 3) * 4;
            float4 v = *(const float4*)(Ab + (size_t)r*K + k0 + kq);
            v.x = to_tf32(v.x); v.y = to_tf32(v.y);
            v.z = to_tf32(v.z); v.w = to_tf32(v.w);
            *(float4*)(&As[r][kq]) = v;
        }
        // ---- stage B tile (16x128) ----
        #pragma unroll
        for (int i = 0; i < 2; i++) {
            const int f = tid + i*256;
            const int kr = f >> 5, nq = (f & 31) * 4;
            float4 v = *(const float4*)(Bb + (size_t)(k0 + kr)*N + nq);
            v.x = to_tf32(v.x); v.y = to_tf32(v.y);
            v.z = to_tf32(v.z); v.w = to_tf32(v.w);
            *(float4*)(&Bs[kr][nq]) = v;
        }
        __syncthreads();

        #pragma unroll
        for (int kk = 0; kk < 16; kk += 8) {
            uint32_t af[2][4];
            #pragma unroll
            for (int mi = 0; mi < 2; mi++) {
                const int m0 = mBase + mi*16;
                af[mi][0] = __float_as_uint(As[m0 + g    ][kk + t4    ]);
                af[mi][1] = __float_as_uint(As[m0 + g + 8][kk + t4    ]);
                af[mi][2] = __float_as_uint(As[m0 + g    ][kk + t4 + 4]);
                af[mi][3] = __float_as_uint(As[m0 + g + 8][kk + t4 + 4]);
            }
            uint32_t bf[8][2];
            #pragma unroll
            for (int ni = 0; ni < 8; ni++) {
                const int n0 = nBase + ni*8 + g;
                bf[ni][0] = __float_as_uint(Bs[kk + t4    ][n0]);
                bf[ni][1] = __float_as_uint(Bs[kk + t4 + 4][n0]);
            }
            #pragma unroll
            for (int mi = 0; mi < 2; mi++)
                #pragma unroll
                for (int ni = 0; ni < 8; ni++)
                    mma_tf32(acc[mi][ni], af[mi], bf[ni]);
        }
        __syncthreads();
    }

    // ---- epilogue ----
    const int rowTile = blockIdx.y * 128;
    const int colTile = blockIdx.x * 128;
    #pragma unroll
    for (int mi = 0; mi < 2; mi++) {
        const int r0 = rowTile + mBase + mi*16 + g;
        #pragma unroll
        for (int ni = 0; ni < 8; ni++) {
            const int c = colTile + nBase + ni*8 + t4*2;
            const float2 bz = *(const float2*)(bias + c);
            float v0 = acc[mi][ni][0] + bz.x;
            float v1 = acc[mi][ni][1] + bz.y;
            float v2 = acc[mi][ni][2] + bz.x;
            float v3 = acc[mi][ni][3] + bz.y;
            const size_t off0 = (size_t)r0 * N + c;
            const size_t off1 = (size_t)(r0 + 8) * N + c;
            if (RES) {
                const float2 r0v = *(const float2*)(res + off0);
                const float2 r1v = *(const float2*)(res + off1);
                v0 += r0v.x; v1 += r0v.y; v2 += r1v.x; v3 += r1v.y;
            }
            if (ACT == 1) {
                v0 = gelu_f(v0); v1 = gelu_f(v1);
                v2 = gelu_f(v2); v3 = gelu_f(v3);
            }
            *(float2*)(C + off0) = make_float2(v0, v1);
            *(float2*)(C + off1) = make_float2(v2, v3);
        }
    }
}

// ---------------- attention: block per (b, head), 64 threads -------------
__global__ void __launch_bounds__(64) attn_kernel(const float* __restrict__ qkv,
                                                  float* __restrict__ out)
{
    const int bh = blockIdx.x;
    const int b = bh >> 3, h = bh & 7;
    const int tid = threadIdx.x;
    __shared__ float q[NPATCH][DH], k[NPATCH][DH], v[NPATCH][DH];
    __shared__ float att[NPATCH][NPATCH];

    const float* base = qkv + (size_t)(b*NPATCH) * (3*HID) + h*DH;
    for (int idx = tid; idx < NPATCH*DH; idx += 64) {
        int p = idx >> 6, d = idx & 63;
        q[p][d] = base[(size_t)p*(3*HID) + d];
        k[p][d] = base[(size_t)p*(3*HID) + HID + d];
        v[p][d] = base[(size_t)p*(3*HID) + 2*HID + d];
    }
    __syncthreads();

    for (int p = tid; p < NPATCH*NPATCH; p += 64) {
        int i = p / NPATCH, j = p % NPATCH;
        float s = 0.f;
        #pragma unroll
        for (int d = 0; d < DH; d++) s = fmaf(q[i][d], k[j][d], s);
        att[i][j] = s * 0.125f;
    }
    __syncthreads();

    if (tid < NPATCH) {
        float mx = -1e30f;
        #pragma unroll
        for (int j = 0; j < NPATCH; j++) mx = fmaxf(mx, att[tid][j]);
        float e[NPATCH], sum = 0.f;
        #pragma unroll
        for (int j = 0; j < NPATCH; j++) { e[j] = expf(att[tid][j] - mx); sum += e[j]; }
        const float r = 1.f / sum;
        #pragma unroll
        for (int j = 0; j < NPATCH; j++) att[tid][j] = e[j] * r;
    }
    __syncthreads();

    const int d = tid;
    #pragma unroll
    for (int i = 0; i < NPATCH; i++) {
        float s = 0.f;
        #pragma unroll
        for (int j = 0; j < NPATCH; j++) s = fmaf(att[i][j], v[j][d], s);
        out[(size_t)(b*NPATCH + i)*HID + h*DH + d] = s;
    }
}

// ---------------- final tiny GEMM: (4096x128)@(128x3) --------------------
__global__ void cls3_kernel(const float* __restrict__ C2,
                            const float* __restrict__ w3,
                            const float* __restrict__ b3,
                            float* __restrict__ out)
{
    const int idx = blockIdx.x * blockDim.x + threadIdx.x;
    if (idx >= BB*NCLS) return;
    const int b = idx / NCLS, c = idx % NCLS;
    float s = b3[c];
    const float* r = C2 + (size_t)b*128;
    #pragma unroll 8
    for (int k2 = 0; k2 < 128; k2++) s = fmaf(r[k2], w3[k2*NCLS + c], s);
    out[idx] = s;
}

// ---------------- host launcher ------------------------------------------
static inline float* sym_addr(const void* s) {
    void* p = nullptr;
    cudaGetSymbolAddress(&p, s);
    return (float*)p;
}

extern "C" void kernel_launch(void* const* d_in, const int* in_sizes, int n_in,
                              void* d_out, int out_size)
{
    const float* x      = (const float*)d_in[0];
    const float* in_w   = (const float*)d_in[1];
    const float* in_b   = (const float*)d_in[2];
    const float* pe_w   = (const float*)d_in[3];
    const float* pe_b   = (const float*)d_in[4];
    const float* ln1_w  = (const float*)d_in[5];
    const float* ln1_b  = (const float*)d_in[6];
    const float* qkv_w  = (const float*)d_in[7];
    const float* qkv_b  = (const float*)d_in[8];
    const float* out_w  = (const float*)d_in[9];
    const float* out_b  = (const float*)d_in[10];
    const float* ln2_w  = (const float*)d_in[11];
    const float* ln2_b  = (const float*)d_in[12];
    const float* mlp_w1 = (const float*)d_in[13];
    const float* mlp_b1 = (const float*)d_in[14];
    const float* mlp_w2 = (const float*)d_in[15];
    const float* mlp_b2 = (const float*)d_in[16];
    const float* cls_w1 = (const float*)d_in[17];
    const float* cls_b1 = (const float*)d_in[18];
    const float* cls_w2 = (const float*)d_in[19];
    const float* cls_b2 = (const float*)d_in[20];
    const float* cls_w3 = (const float*)d_in[21];
    const float* cls_b3 = (const float*)d_in[22];

    float* F   = sym_addr(g_feats);
    float* PEW = sym_addr(g_pew);
    float* H   = sym_addr(g_h);
    float* H2  = sym_addr(g_h2);
    float* Nn  = sym_addr(g_n);
    float* QKV = sym_addr(g_qkv);
    float* O   = sym_addr(g_o);
    float* G   = sym_addr(g_g);
    float* C1  = sym_addr(g_c1);
    float* C2  = sym_addr(g_c2);

    // stage 1: features (padded layout) + padded patch-embed weight
    factors_kernel<<<BB, TT>>>(x, in_w, in_b, F);
    pad_pew_kernel<<<(PDIMP*HID + 255)/256, 256>>>(pe_w, PEW);

    // patch embed: (TOK x 96) @ (96 x 512)
    mma_gemm<0,false><<<dim3(HID/128, TOK/128), 256>>>(F, PEW, pe_b, nullptr, H, TOK, HID, PDIMP);

    for (int i = 0; i < NL; i++) {
        ln_kernel<<<TOK, 128>>>(H, ln1_w + i*HID, ln1_b + i*HID, Nn);
        mma_gemm<0,false><<<dim3(3*HID/128, TOK/128), 256>>>(
            Nn, qkv_w + (size_t)i*HID*3*HID, qkv_b + (size_t)i*3*HID, nullptr, QKV, TOK, 3*HID, HID);
        attn_kernel<<<BB*HEADS, 64>>>(QKV, O);
        mma_gemm<0,true><<<dim3(HID/128, TOK/128), 256>>>(
            O, out_w + (size_t)i*HID*HID, out_b + (size_t)i*HID, H, H2, TOK, HID, HID);
        ln_kernel<<<TOK, 128>>>(H2, ln2_w + i*HID, ln2_b + i*HID, Nn);
        mma_gemm<1,false><<<dim3(MLPH/128, TOK/128), 256>>>(
            Nn, mlp_w1 + (size_t)i*HID*MLPH, mlp_b1 + (size_t)i*MLPH, nullptr, G, TOK, MLPH, HID);
        mma_gemm<0,true><<<dim3(HID/128, TOK/128), 256>>>(
            G, mlp_w2 + (size_t)i*MLPH*HID, mlp_b2 + (size_t)i*HID, H2, H, TOK, HID, MLPH);
    }

    // classifier: H viewed as (4096 x 6144)
    mma_gemm<1,false><<<dim3(512/128, BB/128), 256>>>(H, cls_w1, cls_b1, nullptr, C1, BB, 512, HID*NPATCH);
    mma_gemm<1,false><<<dim3(128/128, BB/128), 256>>>(C1, cls_w2, cls_b2, nullptr, C2, BB, 128, 512);
    cls3_kernel<<<(BB*NCLS + 127)/128, 128>>>(C2, cls_w3, cls_b3, (float*)d_out);
}

// round 11
// speedup vs baseline: 3.0066x; 1.1604x over previous
#include <cuda_runtime.h>
#include <cuda_bf16.h>
#include <math.h>
#include <stdint.h>

// ---------------- problem constants ----------------
#define BB    4096
#define TT    96
#define FRAW  5
#define TOTF  11
#define HID   512
#define NL    4
#define HEADS 8
#define DH    64
#define PATCH 8
#define NPATCH 12
#define PDIM  88
#define PDIMP 96
#define TOK   (BB*NPATCH)   // 49152
#define MLPH  2048
#define NCLS  3

// ---------------- scratch (static device, no allocation) ----------------
__device__ float g_feats[(size_t)TOK*PDIMP];
__device__ float g_h  [(size_t)TOK*HID];
__device__ float g_h2 [(size_t)TOK*HID];
__device__ float g_n  [(size_t)TOK*HID];
__device__ float g_qkv[(size_t)TOK*3*HID];
__device__ float g_o  [(size_t)TOK*HID];
__device__ float g_g  [(size_t)TOK*MLPH];
__device__ float g_c1 [(size_t)BB*512];
__device__ float g_c2 [(size_t)BB*128];
// tf32-pre-rounded weight copies (same [K][N] layout; pe padded to 96 rows)
__device__ float g_pe_wr [(size_t)PDIMP*HID];
__device__ float g_qkv_wr[(size_t)NL*HID*3*HID];
__device__ float g_out_wr[(size_t)NL*HID*HID];
__device__ float g_m1_wr [(size_t)NL*HID*MLPH];
__device__ float g_m2_wr [(size_t)NL*MLPH*HID];
__device__ float g_c1_wr [(size_t)HID*NPATCH*512];
__device__ float g_c2_wr [(size_t)512*128];

__device__ __forceinline__ float gelu_f(float x) {
    return 0.5f * x * (1.f + erff(x * 0.7071067811865476f));
}
__device__ __forceinline__ float to_tf32(float x) {
    uint32_t u;
    asm("cvt.rna.tf32.f32 %0, %1;" : "=r"(u) : "f"(x));
    return __uint_as_float(u);
}
__device__ __forceinline__ uint32_t s2u(const void* p) {
    uint32_t a;
    asm("{ .reg .u64 t; cvta.to.shared.u64 t, %1; cvt.u32.u64 %0, t; }" : "=r"(a) : "l"(p));
    return a;
}
__device__ __forceinline__ void mma_tf32(float c[4], const uint32_t a[4], const uint32_t b[2]) {
    asm volatile(
        "mma.sync.aligned.m16n8k8.row.col.f32.tf32.tf32.f32 "
        "{%0,%1,%2,%3}, {%4,%5,%6,%7}, {%8,%9}, {%0,%1,%2,%3};"
        : "+f"(c[0]), "+f"(c[1]), "+f"(c[2]), "+f"(c[3])
        : "r"(a[0]), "r"(a[1]), "r"(a[2]), "r"(a[3]), "r"(b[0]), "r"(b[1]));
}

// ---------------- weight pre-round (elementwise) --------------------------
__global__ void round_copy(const float* __restrict__ src, float* __restrict__ dst, int n)
{
    const int i = blockIdx.x * blockDim.x + threadIdx.x;
    if (i < n) dst[i] = to_tf32(src[i]);
}
// pe_w [88][512] -> [96][512] rounded, zero pad rows
__global__ void pad_pew_kernel(const float* __restrict__ pe_w, float* __restrict__ dst)
{
    const int idx = blockIdx.x * blockDim.x + threadIdx.x;
    if (idx >= PDIMP*HID) return;
    const int k = idx / HID;
    dst[idx] = (k < PDIM) ? to_tf32(pe_w[idx]) : 0.f;
}

// ---------------- pipelined tf32 tensor GEMM ------------------------------
// C = act(A@B + bias [+res]) [RND: round C to tf32]
// A: MxK row-major, PRE-ROUNDED to tf32. B: KxN row-major, pre-rounded.
// M%128==0, N%128==0, K%16==0. Block 128x128x16, 8 warps, 3-stage cp.async.
#define SA 20     // As row stride (floats)
#define SB 136    // Bs row stride (floats)
#define STG_F (128*SA + 16*SB)   // floats per stage = 2560+2176 = 4736
#define NSTAGE 3

template<int ACT, int RES, int RND>
__global__ void __launch_bounds__(256, 2) mma_gemm_pipe(
    const float* __restrict__ A, const float* __restrict__ Bw,
    const float* __restrict__ bias, const float* __restrict__ res,
    float* __restrict__ C, int M, int N, int K)
{
    extern __shared__ float dsm[];
    const int tid  = threadIdx.x;
    const int lane = tid & 31;
    const int wid  = tid >> 5;
    const int g    = lane >> 2;
    const int t4   = lane & 3;
    const int wm   = wid & 3;
    const int wn   = wid >> 2;
    const int mBase = wm * 32;
    const int nBase = wn * 64;

    const float* Ab = A  + (size_t)blockIdx.y * 128 * K;
    const float* Bb = Bw + (size_t)blockIdx.x * 128;
    const int nk = K >> 4;

    const uint32_t smemBase = s2u(dsm);

    // loader coords (2 float4 each for A and B per thread per stage)
    const int ar0 = tid >> 2,          akq0 = (tid & 3);
    const int ar1 = (tid + 256) >> 2,  akq1 = (tid & 3);
    const int bkr0 = tid >> 5,         bnq0 = (tid & 31);
    const int bkr1 = (tid + 256) >> 5, bnq1 = (tid & 31);

// NOTE: macro-local variable is kbi (NOT kb) — ISSUE(kb+2) must capture the
// loop variable, not shadow it (R7 bug: `const int kb = (kb+2)` read its own
// uninitialized self).
#define ISSUE(kb_) do {                                                           \
    const int kbi = (kb_);                                                        \
    if (kbi < nk) {                                                               \
        const int k0 = kbi << 4;                                                  \
        const uint32_t sA = smemBase + (uint32_t)((kbi % NSTAGE) * STG_F) * 4u;   \
        const uint32_t sB = sA + 128*SA*4;                                        \
        asm volatile("cp.async.cg.shared.global [%0], [%1], 16;" ::               \
            "r"(sA + (ar0*SA + akq0*4)*4), "l"(Ab + (size_t)ar0*K + k0 + akq0*4));\
        asm volatile("cp.async.cg.shared.global [%0], [%1], 16;" ::               \
            "r"(sA + (ar1*SA + akq1*4)*4), "l"(Ab + (size_t)ar1*K + k0 + akq1*4));\
        asm volatile("cp.async.cg.shared.global [%0], [%1], 16;" ::               \
            "r"(sB + (bkr0*SB + bnq0*4)*4), "l"(Bb + (size_t)(k0+bkr0)*N + bnq0*4));\
        asm volatile("cp.async.cg.shared.global [%0], [%1], 16;" ::               \
            "r"(sB + (bkr1*SB + bnq1*4)*4), "l"(Bb + (size_t)(k0+bkr1)*N + bnq1*4));\
    }                                                                             \
    asm volatile("cp.async.commit_group;" ::: "memory");                          \
} while (0)

    ISSUE(0);
    ISSUE(1);

    float acc[2][8][4] = {};

    for (int kb = 0; kb < nk; kb++) {
        asm volatile("cp.async.wait_group 1;" ::: "memory");
        __syncthreads();
        ISSUE(kb + 2);

        const float* As = dsm + (kb % NSTAGE) * STG_F;
        const float* Bs = As + 128*SA;

        #pragma unroll
        for (int kk = 0; kk < 16; kk += 8) {
            uint32_t af[2][4];
            #pragma unroll
            for (int mi = 0; mi < 2; mi++) {
                const int m0 = mBase + mi*16;
                af[mi][0] = __float_as_uint(As[(m0 + g    )*SA + kk + t4    ]);
                af[mi][1] = __float_as_uint(As[(m0 + g + 8)*SA + kk + t4    ]);
                af[mi][2] = __float_as_uint(As[(m0 + g    )*SA + kk + t4 + 4]);
                af[mi][3] = __float_as_uint(As[(m0 + g + 8)*SA + kk + t4 + 4]);
            }
            uint32_t bf[8][2];
            #pragma unroll
            for (int ni = 0; ni < 8; ni++) {
                const int n0 = nBase + ni*8 + g;
                bf[ni][0] = __float_as_uint(Bs[(kk + t4    )*SB + n0]);
                bf[ni][1] = __float_as_uint(Bs[(kk + t4 + 4)*SB + n0]);
            }
            #pragma unroll
            for (int mi = 0; mi < 2; mi++)
                #pragma unroll
                for (int ni = 0; ni < 8; ni++)
                    mma_tf32(acc[mi][ni], af[mi], bf[ni]);
        }
    }
#undef ISSUE

    // ---- epilogue ----
    const int rowTile = blockIdx.y * 128;
    const int colTile = blockIdx.x * 128;
    #pragma unroll
    for (int mi = 0; mi < 2; mi++) {
        const int r0 = rowTile + mBase + mi*16 + g;
        #pragma unroll
        for (int ni = 0; ni < 8; ni++) {
            const int c = colTile + nBase + ni*8 + t4*2;
            const float2 bz = *(const float2*)(bias + c);
            float v0 = acc[mi][ni][0] + bz.x;
            float v1 = acc[mi][ni][1] + bz.y;
            float v2 = acc[mi][ni][2] + bz.x;
            float v3 = acc[mi][ni][3] + bz.y;
            const size_t off0 = (size_t)r0 * N + c;
            const size_t off1 = (size_t)(r0 + 8) * N + c;
            if (RES) {
                const float2 r0v = *(const float2*)(res + off0);
                const float2 r1v = *(const float2*)(res + off1);
                v0 += r0v.x; v1 += r0v.y; v2 += r1v.x; v3 += r1v.y;
            }
            if (ACT == 1) {
                v0 = gelu_f(v0); v1 = gelu_f(v1);
                v2 = gelu_f(v2); v3 = gelu_f(v3);
            }
            if (RND) {
                v0 = to_tf32(v0); v1 = to_tf32(v1);
                v2 = to_tf32(v2); v3 = to_tf32(v3);
            }
            *(float2*)(C + off0) = make_float2(v0, v1);
            *(float2*)(C + off1) = make_float2(v2, v3);
        }
    }
}

// ---------------- synchronous tf32 GEMM (rounds A at staging) -------------
// used only where A is NOT pre-rounded (cls1: A = residual stream H)
template<int ACT, int RES, int RND>
__global__ void __launch_bounds__(256, 2) mma_gemm_sync(
    const float* __restrict__ A, const float* __restrict__ Bw,
    const float* __restrict__ bias, const float* __restrict__ res,
    float* __restrict__ C, int M, int N, int K)
{
    __shared__ float As[128][SA];
    __shared__ float Bs[16][SB];
    const int tid  = threadIdx.x;
    const int lane = tid & 31;
    const int wid  = tid >> 5;
    const int g    = lane >> 2;
    const int t4   = lane & 3;
    const int wm   = wid & 3;
    const int wn   = wid >> 2;
    const int mBase = wm * 32;
    const int nBase = wn * 64;

    const float* Ab = A  + (size_t)blockIdx.y * 128 * K;
    const float* Bb = Bw + (size_t)blockIdx.x * 128;

    float acc[2][8][4] = {};

    for (int k0 = 0; k0 < K; k0 += 16) {
        #pragma unroll
        for (int i = 0; i < 2; i++) {
            const int f = tid + i*256;
            const int r = f >> 2, kq = (f & 3) * 4;
            float4 v = *(const float4*)(Ab + (size_t)r*K + k0 + kq);
            v.x = to_tf32(v.x); v.y = to_tf32(v.y);
            v.z = to_tf32(v.z); v.w = to_tf32(v.w);
            *(float4*)(&As[r][kq]) = v;
        }
        #pragma unroll
        for (int i = 0; i < 2; i++) {
            const int f = tid + i*256;
            const int kr = f >> 5, nq = (f & 31) * 4;
            *(float4*)(&Bs[kr][nq]) = *(const float4*)(Bb + (size_t)(k0 + kr)*N + nq);
        }
        __syncthreads();

        #pragma unroll
        for (int kk = 0; kk < 16; kk += 8) {
            uint32_t af[2][4];
            #pragma unroll
            for (int mi = 0; mi < 2; mi++) {
                const int m0 = mBase + mi*16;
                af[mi][0] = __float_as_uint(As[m0 + g    ][kk + t4    ]);
                af[mi][1] = __float_as_uint(As[m0 + g + 8][kk + t4    ]);
                af[mi][2] = __float_as_uint(As[m0 + g    ][kk + t4 + 4]);
                af[mi][3] = __float_as_uint(As[m0 + g + 8][kk + t4 + 4]);
            }
            uint32_t bf[8][2];
            #pragma unroll
            for (int ni = 0; ni < 8; ni++) {
                const int n0 = nBase + ni*8 + g;
                bf[ni][0] = __float_as_uint(Bs[kk + t4    ][n0]);
                bf[ni][1] = __float_as_uint(Bs[kk + t4 + 4][n0]);
            }
            #pragma unroll
            for (int mi = 0; mi < 2; mi++)
                #pragma unroll
                for (int ni = 0; ni < 8; ni++)
                    mma_tf32(acc[mi][ni], af[mi], bf[ni]);
        }
        __syncthreads();
    }

    const int rowTile = blockIdx.y * 128;
    const int colTile = blockIdx.x * 128;
    #pragma unroll
    for (int mi = 0; mi < 2; mi++) {
        const int r0 = rowTile + mBase + mi*16 + g;
        #pragma unroll
        for (int ni = 0; ni < 8; ni++) {
            const int c = colTile + nBase + ni*8 + t4*2;
            const float2 bz = *(const float2*)(bias + c);
            float v0 = acc[mi][ni][0] + bz.x;
            float v1 = acc[mi][ni][1] + bz.y;
            float v2 = acc[mi][ni][2] + bz.x;
            float v3 = acc[mi][ni][3] + bz.y;
            const size_t off0 = (size_t)r0 * N + c;
            const size_t off1 = (size_t)(r0 + 8) * N + c;
            if (RES) {
                const float2 r0v = *(const float2*)(res + off0);
                const float2 r1v = *(const float2*)(res + off1);
                v0 += r0v.x; v1 += r0v.y; v2 += r1v.x; v3 += r1v.y;
            }
            if (ACT == 1) {
                v0 = gelu_f(v0); v1 = gelu_f(v1);
                v2 = gelu_f(v2); v3 = gelu_f(v3);
            }
            if (RND) {
                v0 = to_tf32(v0); v1 = to_tf32(v1);
                v2 = to_tf32(v2); v3 = to_tf32(v3);
            }
            *(float2*)(C + off0) = make_float2(v0, v1);
            *(float2*)(C + off1) = make_float2(v2, v3);
        }
    }
}

// ---------------- stage 1: factor engineering + time-norm ----------------
// output rounded to tf32 (feeds GEMM A only)
__global__ void factors_kernel(const float* __restrict__ x,
                               const float* __restrict__ in_w,
                               const float* __restrict__ in_b,
                               float* __restrict__ feats)
{
    __shared__ float cl[TT], vol[TT];
    __shared__ float sf[TT][TOTF];
    __shared__ float mean_s[TOTF], inv_s[TOTF];
    const int b = blockIdx.x;
    const int t = threadIdx.x;
    const float* xb = x + (size_t)b * TT * FRAW;

    if (t < TT) { cl[t] = xb[t*FRAW + 3]; vol[t] = xb[t*FRAW + 4]; }
    __syncthreads();

    if (t < TT) {
        const float a13 = 2.f/13.f, a27 = 2.f/27.f, a14 = 1.f/14.f;
        float e13 = cl[0], e27 = cl[0];
        float eg = 0.f, el = 0.f;
        for (int j = 1; j <= t; j++) {
            float c = cl[j];
            e13 = a13*c + (1.f - a13)*e13;
            e27 = a27*c + (1.f - a27)*e27;
            float d = c - cl[j-1];
            float g = fmaxf(d, 0.f);
            float l = -fminf(d, 0.f);
            eg = a14*g + (1.f - a14)*eg;
            el = a14*l + (1.f - a14)*el;
        }
        float macd = e13 - e27;
        float rs  = eg / (el + 1e-10f);
        float rsi = (100.f - 100.f/(1.f + rs)) * 0.01f;

        float bb = 0.f;
        if (t >= 19) {
            float s = 0.f, s2 = 0.f;
            for (int j = t-19; j <= t; j++) { float c = cl[j]; s += c; s2 += c*c; }
            float m  = s * 0.05f;
            float sq = s2 * 0.05f;
            float sd = sqrtf(fmaxf(sq - m*m, 0.f));
            bb = 4.f * sd / (m + 1e-8f);
        }

        float lr = 0.f, lv = 0.f;
        float svt = vol[t] > 0.f ? vol[t] : 1.f;
        if (t >= 1) {
            float pc = fmaxf(cl[t-1], 1e-8f);
            lr = logf(fmaxf(cl[t], 1e-8f) / pc);
            float svp = vol[t-1] > 0.f ? vol[t-1] : 1.f;
            lv = logf(svt / (svp + 1e-8f));
        }

        float vmr = 1.f;
        if (t >= 19) {
            float s = 0.f;
            for (int j = t-19; j <= t; j++) { float v2 = vol[j] > 0.f ? vol[j] : 1.f; s += v2; }
            vmr = svt / (s * 0.05f + 1e-8f);
        }

        float f6[6] = {macd, rsi, bb, lr, lv, vmr};
        #pragma unroll
        for (int f = 0; f < FRAW; f++) sf[t][f] = xb[t*FRAW + f];
        #pragma unroll
        for (int f = 0; f < 6; f++) {
            float v = f6[f];
            if (!isfinite(v)) v = 0.f;
            sf[t][FRAW + f] = v;
        }
    }
    __syncthreads();

    if (t < TOTF) {
        float s = 0.f;
        for (int j = 0; j < TT; j++) s += sf[j][t];
        mean_s[t] = s / (float)TT;
    }
    __syncthreads();
    if (t < TOTF) {
        float m = mean_s[t], s = 0.f;
        for (int j = 0; j < TT; j++) { float d = sf[j][t] - m; s += d*d; }
        inv_s[t] = rsqrtf(s / (float)TT + 1e-5f);
    }
    __syncthreads();

    if (t < TT) {
        const int token = b*NPATCH + (t / PATCH);
        float* o = feats + (size_t)token*PDIMP + (t % PATCH)*TOTF;
        #pragma unroll
        for (int f = 0; f < TOTF; f++)
            o[f] = to_tf32((sf[t][f] - mean_s[f]) * inv_s[f] * in_w[f] + in_b[f]);
    }
    if (t < NPATCH) {
        float* z = feats + (size_t)(b*NPATCH + t)*PDIMP + PDIM;
        #pragma unroll
        for (int i = 0; i < PDIMP - PDIM; i++) z[i] = 0.f;
    }
}

// ---------------- LayerNorm (output rounded; feeds GEMM A only) ----------
__global__ void __launch_bounds__(128) ln_kernel(const float* __restrict__ X,
                                                 const float* __restrict__ w,
                                                 const float* __restrict__ b,
                                                 float* __restrict__ Y)
{
    const int row = blockIdx.x;
    const int tid = threadIdx.x;
    const float4 v = ((const float4*)(X + (size_t)row*HID))[tid];
    float s = v.x + v.y + v.z + v.w;
    __shared__ float red[4], red2[4];
    #pragma unroll
    for (int o = 16; o; o >>= 1) s += __shfl_down_sync(0xffffffffu, s, o);
    if ((tid & 31) == 0) red[tid >> 5] = s;
    __syncthreads();
    const float m = (red[0]+red[1]+red[2]+red[3]) * (1.f/(float)HID);
    float dx = v.x - m, dy = v.y - m, dz = v.z - m, dw = v.w - m;
    float s2 = dx*dx + dy*dy + dz*dz + dw*dw;
    #pragma unroll
    for (int o = 16; o; o >>= 1) s2 += __shfl_down_sync(0xffffffffu, s2, o);
    if ((tid & 31) == 0) red2[tid >> 5] = s2;
    __syncthreads();
    const float var = (red2[0]+red2[1]+red2[2]+red2[3]) * (1.f/(float)HID);
    const float inv = rsqrtf(var + 1e-5f);
    const int c = tid * 4;
    const float4 wv = *(const float4*)(w + c);
    const float4 bv = *(const float4*)(b + c);
    float4 o4;
    o4.x = to_tf32(dx*inv*wv.x + bv.x);
    o4.y = to_tf32(dy*inv*wv.y + bv.y);
    o4.z = to_tf32(dz*inv*wv.z + bv.z);
    o4.w = to_tf32(dw*inv*wv.w + bv.w);
    ((float4*)(Y + (size_t)row*HID))[tid] = o4;
}

// ---------------- attention (output rounded; feeds GEMM A only) ----------
__global__ void __launch_bounds__(64) attn_kernel(const float* __restrict__ qkv,
                                                  float* __restrict__ out)
{
    const int bh = blockIdx.x;
    const int b = bh >> 3, h = bh & 7;
    const int tid = threadIdx.x;
    __shared__ float q[NPATCH][DH], k[NPATCH][DH], v[NPATCH][DH];
    __shared__ float att[NPATCH][NPATCH];

    const float* base = qkv + (size_t)(b*NPATCH) * (3*HID) + h*DH;
    for (int idx = tid; idx < NPATCH*DH; idx += 64) {
        int p = idx >> 6, d = idx & 63;
        q[p][d] = base[(size_t)p*(3*HID) + d];
        k[p][d] = base[(size_t)p*(3*HID) + HID + d];
        v[p][d] = base[(size_t)p*(3*HID) + 2*HID + d];
    }
    __syncthreads();

    for (int p = tid; p < NPATCH*NPATCH; p += 64) {
        int i = p / NPATCH, j = p % NPATCH;
        float s = 0.f;
        #pragma unroll
        for (int d = 0; d < DH; d++) s = fmaf(q[i][d], k[j][d], s);
        att[i][j] = s * 0.125f;
    }
    __syncthreads();

    if (tid < NPATCH) {
        float mx = -1e30f;
        #pragma unroll
        for (int j = 0; j < NPATCH; j++) mx = fmaxf(mx, att[tid][j]);
        float e[NPATCH], sum = 0.f;
        #pragma unroll
        for (int j = 0; j < NPATCH; j++) { e[j] = expf(att[tid][j] - mx); sum += e[j]; }
        const float r = 1.f / sum;
        #pragma unroll
        for (int j = 0; j < NPATCH; j++) att[tid][j] = e[j] * r;
    }
    __syncthreads();

    const int d = tid;
    #pragma unroll
    for (int i = 0; i < NPATCH; i++) {
        float s = 0.f;
        #pragma unroll
        for (int j = 0; j < NPATCH; j++) s = fmaf(att[i][j], v[j][d], s);
        out[(size_t)(b*NPATCH + i)*HID + h*DH + d] = to_tf32(s);
    }
}

// ---------------- final tiny GEMM: (4096x128)@(128x3) --------------------
__global__ void cls3_kernel(const float* __restrict__ C2,
                            const float* __restrict__ w3,
                            const float* __restrict__ b3,
                            float* __restrict__ out)
{
    const int idx = blockIdx.x * blockDim.x + threadIdx.x;
    if (idx >= BB*NCLS) return;
    const int b = idx / NCLS, c = idx % NCLS;
    float s = b3[c];
    const float* r = C2 + (size_t)b*128;
    #pragma unroll 8
    for (int k2 = 0; k2 < 128; k2++) s = fmaf(r[k2], w3[k2*NCLS + c], s);
    out[idx] = s;
}

// ---------------- host launcher ------------------------------------------
static inline float* sym_addr(const void* s) {
    void* p = nullptr;
    cudaGetSymbolAddress(&p, s);
    return (float*)p;
}

#define PIPE_SMEM (NSTAGE * STG_F * 4)

template<int ACT, int RES, int RND>
static void launch_pipe(const float* A, const float* B, const float* bias,
                        const float* res, float* C, int M, int N, int K)
{
    static bool attr_done = false;
    if (!attr_done) {
        cudaFuncSetAttribute(mma_gemm_pipe<ACT,RES,RND>,
                             cudaFuncAttributeMaxDynamicSharedMemorySize, PIPE_SMEM);
        attr_done = true;
    }
    mma_gemm_pipe<ACT,RES,RND><<<dim3(N/128, M/128), 256, PIPE_SMEM>>>(A, B, bias, res, C, M, N, K);
}

extern "C" void kernel_launch(void* const* d_in, const int* in_sizes, int n_in,
                              void* d_out, int out_size)
{
    const float* x      = (const float*)d_in[0];
    const float* in_w   = (const float*)d_in[1];
    const float* in_b   = (const float*)d_in[2];
    const float* pe_w   = (const float*)d_in[3];
    const float* pe_b   = (const float*)d_in[4];
    const float* ln1_w  = (const float*)d_in[5];
    const float* ln1_b  = (const float*)d_in[6];
    const float* qkv_w  = (const float*)d_in[7];
    const float* qkv_b  = (const float*)d_in[8];
    const float* out_w  = (const float*)d_in[9];
    const float* out_b  = (const float*)d_in[10];
    const float* ln2_w  = (const float*)d_in[11];
    const float* ln2_b  = (const float*)d_in[12];
    const float* mlp_w1 = (const float*)d_in[13];
    const float* mlp_b1 = (const float*)d_in[14];
    const float* mlp_w2 = (const float*)d_in[15];
    const float* mlp_b2 = (const float*)d_in[16];
    const float* cls_w1 = (const float*)d_in[17];
    const float* cls_b1 = (const float*)d_in[18];
    const float* cls_w2 = (const float*)d_in[19];
    const float* cls_b2 = (const float*)d_in[20];
    const float* cls_w3 = (const float*)d_in[21];
    const float* cls_b3 = (const float*)d_in[22];

    float* F   = sym_addr(g_feats);
    float* H   = sym_addr(g_h);
    float* H2  = sym_addr(g_h2);
    float* Nn  = sym_addr(g_n);
    float* QKV = sym_addr(g_qkv);
    float* O   = sym_addr(g_o);
    float* G   = sym_addr(g_g);
    float* C1  = sym_addr(g_c1);
    float* C2  = sym_addr(g_c2);
    float* PEr = sym_addr(g_pe_wr);
    float* QKr = sym_addr(g_qkv_wr);
    float* OUr = sym_addr(g_out_wr);
    float* M1r = sym_addr(g_m1_wr);
    float* M2r = sym_addr(g_m2_wr);
    float* C1r = sym_addr(g_c1_wr);
    float* C2r = sym_addr(g_c2_wr);

    // pre-round weights to tf32 (same layout; pe padded 88->96 rows)
    pad_pew_kernel<<<(PDIMP*HID + 255)/256, 256>>>(pe_w, PEr);
    round_copy<<<(NL*HID*3*HID + 255)/256, 256>>>(qkv_w,  QKr, NL*HID*3*HID);
    round_copy<<<(NL*HID*HID   + 255)/256, 256>>>(out_w,  OUr, NL*HID*HID);
    round_copy<<<(NL*HID*MLPH  + 255)/256, 256>>>(mlp_w1, M1r, NL*HID*MLPH);
    round_copy<<<(NL*MLPH*HID  + 255)/256, 256>>>(mlp_w2, M2r, NL*MLPH*HID);
    round_copy<<<(HID*NPATCH*512 + 255)/256, 256>>>(cls_w1, C1r, HID*NPATCH*512);
    round_copy<<<(512*128      + 255)/256, 256>>>(cls_w2, C2r, 512*128);

    factors_kernel<<<BB, TT>>>(x, in_w, in_b, F);

    // patch embed: (TOK x 96) @ (96 x 512)
    launch_pipe<0,0,0>(F, PEr, pe_b, nullptr, H, TOK, HID, PDIMP);

    for (int i = 0; i < NL; i++) {
        ln_kernel<<<TOK, 128>>>(H, ln1_w + i*HID, ln1_b + i*HID, Nn);
        launch_pipe<0,0,0>(Nn, QKr + (size_t)i*HID*3*HID, qkv_b + (size_t)i*3*HID,
                           nullptr, QKV, TOK, 3*HID, HID);
        attn_kernel<<<BB*HEADS, 64>>>(QKV, O);
        launch_pipe<0,1,0>(O, OUr + (size_t)i*HID*HID, out_b + (size_t)i*HID,
                           H, H2, TOK, HID, HID);
        ln_kernel<<<TOK, 128>>>(H2, ln2_w + i*HID, ln2_b + i*HID, Nn);
        launch_pipe<1,0,1>(Nn, M1r + (size_t)i*HID*MLPH, mlp_b1 + (size_t)i*MLPH,
                           nullptr, G, TOK, MLPH, HID);
        launch_pipe<0,1,0>(G, M2r + (size_t)i*MLPH*HID, mlp_b2 + (size_t)i*HID,
                           H2, H, TOK, HID, MLPH);
    }

    // classifier: H (fp32 residual stream) -> sync kernel rounds A at staging
    mma_gemm_sync<1,0,1><<<dim3(512/128, BB/128), 256>>>(
        H, C1r, cls_b1, nullptr, C1, BB, 512, HID*NPATCH);
    launch_pipe<1,0,1>(C1, C2r, cls_b2, nullptr, C2, BB, 128, 512);
    cls3_kernel<<<(BB*NCLS + 127)/128, 128>>>(C2, cls_w3, cls_b3, (float*)d_out);
}